// round 1
// baseline (speedup 1.0000x reference)
#include <cuda_runtime.h>
#include <math.h>

// Problem constants
constexpr int B   = 4;
constexpr int S   = 1024;
constexpr int DIM = 2048;
constexpr int H   = 16;
constexpr int HD  = 128;
constexpr int M   = B * S;          // 4096 rows
constexpr float SCALE = 0.08838834764831845f;  // 1/sqrt(128)

// Scratch (allocation-free rule: __device__ globals)
__device__ float g_q[(size_t)M * DIM];
__device__ float g_k[(size_t)M * DIM];
__device__ float g_v[(size_t)M * DIM];
__device__ float g_ctx[(size_t)M * DIM];

// ---------------------------------------------------------------------------
// GEMM: C[M,N] = A[M,K] @ W[N,K]^T + bias, optional fused RoPE on output.
// Tiles: 128x128 block, BK=16, 256 threads, 8x8 per-thread microtile.
// ---------------------------------------------------------------------------
template <int ROPE>
__global__ __launch_bounds__(256)
void gemm_kernel(const float* __restrict__ A, const float* __restrict__ W,
                 const float* __restrict__ bias,
                 const float* __restrict__ cosb, const float* __restrict__ sinb,
                 float* __restrict__ C)
{
    constexpr int K = DIM, N = DIM;
    __shared__ float As[16][128];
    __shared__ float Bs[16][128];

    const int tid = threadIdx.x;
    const int tx = tid & 15, ty = tid >> 4;
    const int bm = blockIdx.y * 128, bn = blockIdx.x * 128;

    const int r0 = ty * 4, r1 = 64 + ty * 4;
    const int c0 = tx * 4, c1 = 64 + tx * 4;

    float acc[8][8];
#pragma unroll
    for (int i = 0; i < 8; i++)
#pragma unroll
        for (int j = 0; j < 8; j++) acc[i][j] = 0.f;

    for (int k0 = 0; k0 < K; k0 += 16) {
#pragma unroll
        for (int u = 0; u < 2; u++) {
            int i = tid + u * 256;          // 0..511
            int row = i >> 2;               // 0..127
            int kk  = (i & 3) << 2;         // 0,4,8,12
            float4 va = *(const float4*)(A + (size_t)(bm + row) * K + k0 + kk);
            As[kk + 0][row] = va.x; As[kk + 1][row] = va.y;
            As[kk + 2][row] = va.z; As[kk + 3][row] = va.w;
            float4 vb = *(const float4*)(W + (size_t)(bn + row) * K + k0 + kk);
            Bs[kk + 0][row] = vb.x; Bs[kk + 1][row] = vb.y;
            Bs[kk + 2][row] = vb.z; Bs[kk + 3][row] = vb.w;
        }
        __syncthreads();
#pragma unroll
        for (int kk = 0; kk < 16; kk++) {
            float a[8], b[8];
            *(float4*)(a)     = *(const float4*)&As[kk][r0];
            *(float4*)(a + 4) = *(const float4*)&As[kk][r1];
            *(float4*)(b)     = *(const float4*)&Bs[kk][c0];
            *(float4*)(b + 4) = *(const float4*)&Bs[kk][c1];
#pragma unroll
            for (int i = 0; i < 8; i++)
#pragma unroll
                for (int j = 0; j < 8; j++) acc[i][j] += a[i] * b[j];
        }
        __syncthreads();
    }

    // Epilogue: bias (+ RoPE), float4 stores
#pragma unroll
    for (int i = 0; i < 8; i++) {
        const int row = bm + ((i < 4) ? (r0 + i) : (r1 + i - 4));
        const int s   = row & (S - 1);
#pragma unroll
        for (int jj = 0; jj < 2; jj++) {
            const int cb = bn + ((jj == 0) ? c0 : c1);
            float v0 = acc[i][jj * 4 + 0] + bias[cb + 0];
            float v1 = acc[i][jj * 4 + 1] + bias[cb + 1];
            float v2 = acc[i][jj * 4 + 2] + bias[cb + 2];
            float v3 = acc[i][jj * 4 + 3] + bias[cb + 3];
            if (ROPE) {
                const int d0 = cb & (HD - 1);          // even, multiple of 4
                const int f0 = (d0 >> 1);
                const float c_0 = cosb[s * 64 + f0],     s_0 = sinb[s * 64 + f0];
                const float c_1 = cosb[s * 64 + f0 + 1], s_1 = sinb[s * 64 + f0 + 1];
                float o0 = v0 * c_0 - v1 * s_0;
                float o1 = v0 * s_0 + v1 * c_0;
                float o2 = v2 * c_1 - v3 * s_1;
                float o3 = v2 * s_1 + v3 * c_1;
                v0 = o0; v1 = o1; v2 = o2; v3 = o3;
            }
            *(float4*)(C + (size_t)row * N + cb) = make_float4(v0, v1, v2, v3);
        }
    }
}

// ---------------------------------------------------------------------------
// Flash attention (fp32). One block = (b, h, 64 q-rows). 64-key tiles.
// 256 threads: scores 4x4 microtile, PV 4(rows)x8(dims) microtile.
// ---------------------------------------------------------------------------
constexpr int SMEM_ATTN = (128 * 68 * 2 + 64 * 132 + 64 * 68) * 4;  // 120832 B

__global__ __launch_bounds__(256)
void attn_kernel()
{
    extern __shared__ float sm[];
    float* Qs = sm;                  // [128 d][68]  (q-index minor, padded)
    float* Ks = Qs + 128 * 68;       // [128 d][68]
    float* Vs = Ks + 128 * 68;       // [64 k][132]
    float* Ps = Vs + 64 * 132;       // [64 k][68]

    const int tid = threadIdx.x;
    const int tx = tid & 15, ty = tid >> 4;
    const int qb = blockIdx.x * 64;
    const int h  = blockIdx.y;
    const int b  = blockIdx.z;
    const size_t base = (size_t)b * S * DIM + (size_t)h * HD;

    // Load Q tile transposed: Qs[d][q]
    for (int i = tid; i < 64 * 32; i += 256) {
        int qr = i >> 5;
        int d4 = (i & 31) << 2;
        float4 v = *(const float4*)(g_q + base + (size_t)(qb + qr) * DIM + d4);
        Qs[(d4 + 0) * 68 + qr] = v.x;
        Qs[(d4 + 1) * 68 + qr] = v.y;
        Qs[(d4 + 2) * 68 + qr] = v.z;
        Qs[(d4 + 3) * 68 + qr] = v.w;
    }

    float o[4][8];
#pragma unroll
    for (int i = 0; i < 4; i++)
#pragma unroll
        for (int j = 0; j < 8; j++) o[i][j] = 0.f;
    float rm[4], rl[4];
#pragma unroll
    for (int i = 0; i < 4; i++) { rm[i] = -1e30f; rl[i] = 0.f; }

    const int ntiles = (qb >> 6) + 1;
    for (int t = 0; t < ntiles; t++) {
        const int kb = t * 64;
        __syncthreads();   // protect Ks/Vs (prev PV) before overwrite
        for (int i = tid; i < 64 * 32; i += 256) {
            int kr = i >> 5;
            int d4 = (i & 31) << 2;
            float4 v = *(const float4*)(g_k + base + (size_t)(kb + kr) * DIM + d4);
            Ks[(d4 + 0) * 68 + kr] = v.x;
            Ks[(d4 + 1) * 68 + kr] = v.y;
            Ks[(d4 + 2) * 68 + kr] = v.z;
            Ks[(d4 + 3) * 68 + kr] = v.w;
            float4 w = *(const float4*)(g_v + base + (size_t)(kb + kr) * DIM + d4);
            *(float4*)(Vs + kr * 132 + d4) = w;
        }
        __syncthreads();

        // Scores: 4 q-rows x 4 keys per thread
        float sc[4][4];
#pragma unroll
        for (int i = 0; i < 4; i++)
#pragma unroll
            for (int j = 0; j < 4; j++) sc[i][j] = 0.f;

        for (int d = 0; d < 128; d++) {
            float a[4], bb[4];
            *(float4*)a  = *(const float4*)(Qs + d * 68 + ty * 4);
            *(float4*)bb = *(const float4*)(Ks + d * 68 + tx * 4);
#pragma unroll
            for (int i = 0; i < 4; i++)
#pragma unroll
                for (int j = 0; j < 4; j++) sc[i][j] += a[i] * bb[j];
        }

        const bool diag = (t == ntiles - 1);
#pragma unroll
        for (int i = 0; i < 4; i++)
#pragma unroll
            for (int j = 0; j < 4; j++) {
                float s = sc[i][j] * SCALE;
                if (diag && (kb + tx * 4 + j > qb + ty * 4 + i)) s = -1e30f;
                sc[i][j] = s;
            }

        // Online softmax per q-row (row shared by 16 tx lanes in half-warp)
#pragma unroll
        for (int i = 0; i < 4; i++) {
            float mloc = fmaxf(fmaxf(sc[i][0], sc[i][1]), fmaxf(sc[i][2], sc[i][3]));
#pragma unroll
            for (int off = 1; off < 16; off <<= 1)
                mloc = fmaxf(mloc, __shfl_xor_sync(0xffffffffu, mloc, off));
            const float newm = fmaxf(rm[i], mloc);
            const float corr = __expf(rm[i] - newm);
            rm[i] = newm;
            float p[4], psum = 0.f;
#pragma unroll
            for (int j = 0; j < 4; j++) { p[j] = __expf(sc[i][j] - newm); psum += p[j]; }
#pragma unroll
            for (int off = 1; off < 16; off <<= 1)
                psum += __shfl_xor_sync(0xffffffffu, psum, off);
            rl[i] = rl[i] * corr + psum;
#pragma unroll
            for (int j = 0; j < 8; j++) o[i][j] *= corr;
#pragma unroll
            for (int j = 0; j < 4; j++)
                Ps[(tx * 4 + j) * 68 + ty * 4 + i] = p[j];
        }
        __syncthreads();

        // PV: o[4 rows][8 dims] += P[rows][k] * V[k][dims]
        for (int kk = 0; kk < 64; kk++) {
            float a[4], bb[8];
            *(float4*)a        = *(const float4*)(Ps + kk * 68 + ty * 4);
            *(float4*)bb       = *(const float4*)(Vs + kk * 132 + tx * 4);
            *(float4*)(bb + 4) = *(const float4*)(Vs + kk * 132 + 64 + tx * 4);
#pragma unroll
            for (int i = 0; i < 4; i++)
#pragma unroll
                for (int j = 0; j < 8; j++) o[i][j] += a[i] * bb[j];
        }
    }

    // Normalize and write ctx[b][s][h][d]
#pragma unroll
    for (int i = 0; i < 4; i++) {
        const float inv = 1.f / rl[i];
        const int q = qb + ty * 4 + i;
        float* dst = g_ctx + base + (size_t)q * DIM;
        *(float4*)(dst + tx * 4) =
            make_float4(o[i][0] * inv, o[i][1] * inv, o[i][2] * inv, o[i][3] * inv);
        *(float4*)(dst + 64 + tx * 4) =
            make_float4(o[i][4] * inv, o[i][5] * inv, o[i][6] * inv, o[i][7] * inv);
    }
}

// ---------------------------------------------------------------------------
// Launch
// ---------------------------------------------------------------------------
extern "C" void kernel_launch(void* const* d_in, const int* in_sizes, int n_in,
                              void* d_out, int out_size)
{
    const float* x    = (const float*)d_in[0];
    // d_in[1] = start_pos (0, unused); d_in[4] = mask (causal, applied analytically)
    const float* cosb = (const float*)d_in[2];
    const float* sinb = (const float*)d_in[3];
    const float* wq   = (const float*)d_in[5];
    const float* bq   = (const float*)d_in[6];
    const float* wk   = (const float*)d_in[7];
    const float* bk   = (const float*)d_in[8];
    const float* wv   = (const float*)d_in[9];
    const float* bv   = (const float*)d_in[10];
    const float* wo   = (const float*)d_in[11];
    const float* bo   = (const float*)d_in[12];
    float* out = (float*)d_out;

    float *q, *k, *v, *ctx;
    cudaGetSymbolAddress((void**)&q,   g_q);
    cudaGetSymbolAddress((void**)&k,   g_k);
    cudaGetSymbolAddress((void**)&v,   g_v);
    cudaGetSymbolAddress((void**)&ctx, g_ctx);

    cudaFuncSetAttribute(attn_kernel,
                         cudaFuncAttributeMaxDynamicSharedMemorySize, SMEM_ATTN);

    dim3 gdim(DIM / 128, M / 128);   // (16, 32)
    gemm_kernel<1><<<gdim, 256>>>(x, wq, bq, cosb, sinb, q);
    gemm_kernel<1><<<gdim, 256>>>(x, wk, bk, cosb, sinb, k);
    gemm_kernel<0><<<gdim, 256>>>(x, wv, bv, cosb, sinb, v);

    dim3 adim(S / 64, H, B);         // (16, 16, 4)
    attn_kernel<<<adim, 256, SMEM_ATTN>>>();

    gemm_kernel<0><<<gdim, 256>>>(ctx, wo, bo, cosb, sinb, out);
}

// round 2
// speedup vs baseline: 2.0773x; 2.0773x over previous
#include <cuda_runtime.h>
#include <math.h>
#include <stdint.h>

// Problem constants
constexpr int B   = 4;
constexpr int S   = 1024;
constexpr int DIM = 2048;
constexpr int H   = 16;
constexpr int HD  = 128;
constexpr int M   = B * S;          // 4096 rows
constexpr float SCALE = 0.08838834764831845f;  // 1/sqrt(128)

// Scratch (allocation-free rule: __device__ globals)
__device__ float g_q[(size_t)M * DIM];
__device__ float g_k[(size_t)M * DIM];
__device__ float g_v[(size_t)M * DIM];
__device__ float g_ctx[(size_t)M * DIM];

__device__ __forceinline__ uint32_t f2tf32(float x) {
    uint32_t u;
    asm("cvt.rna.tf32.f32 %0, %1;" : "=r"(u) : "f"(x));
    return u;
}

// ---------------------------------------------------------------------------
// tf32 tensor-core GEMM: C[M,N] = A[M,K] @ W[N,K]^T + bias (+ fused RoPE).
// 128x128 block tile, BK=32, 8 warps (2x4), per-warp 64x32 via m16n8k8.
// ---------------------------------------------------------------------------
template <int ROPE>
__global__ __launch_bounds__(256, 2)
void gemm_tf32(const float* __restrict__ A, const float* __restrict__ W,
               const float* __restrict__ bias,
               const float* __restrict__ cosb, const float* __restrict__ sinb,
               float* __restrict__ C)
{
    constexpr int K = DIM;
    __shared__ uint32_t As[128][36];   // tf32 bits, [row][k], pad 36
    __shared__ uint32_t Bs[128][36];   // tf32 bits, [n-row][k], pad 36

    const int tid  = threadIdx.x;
    const int warp = tid >> 5, lane = tid & 31;
    const int gid  = lane >> 2, qid = lane & 3;
    const int wm   = warp >> 2;        // 0..1 : 64 rows each
    const int wn   = warp & 3;         // 0..3 : 32 cols each
    const int bm   = blockIdx.y * 128, bn = blockIdx.x * 128;

    float acc[4][4][4];                // [mfrag][nfrag][c0..c3]
#pragma unroll
    for (int i = 0; i < 4; i++)
#pragma unroll
        for (int j = 0; j < 4; j++)
#pragma unroll
            for (int c = 0; c < 4; c++) acc[i][j][c] = 0.f;

    for (int k0 = 0; k0 < K; k0 += 32) {
        // Stage 128x32 of A and W into smem, converting fp32 -> tf32 bits.
#pragma unroll
        for (int u = 0; u < 4; u++) {
            const int i   = tid + u * 256;     // 0..1023
            const int row = i >> 3;            // 0..127
            const int kq  = (i & 7) << 2;      // 0,4,...,28
            float4 va = *(const float4*)(A + (size_t)(bm + row) * K + k0 + kq);
            As[row][kq + 0] = f2tf32(va.x);
            As[row][kq + 1] = f2tf32(va.y);
            As[row][kq + 2] = f2tf32(va.z);
            As[row][kq + 3] = f2tf32(va.w);
            float4 vb = *(const float4*)(W + (size_t)(bn + row) * K + k0 + kq);
            Bs[row][kq + 0] = f2tf32(vb.x);
            Bs[row][kq + 1] = f2tf32(vb.y);
            Bs[row][kq + 2] = f2tf32(vb.z);
            Bs[row][kq + 3] = f2tf32(vb.w);
        }
        __syncthreads();

#pragma unroll
        for (int ks = 0; ks < 4; ks++) {
            const int kb = ks * 8;
            uint32_t a[4][4], b[4][2];
#pragma unroll
            for (int mf = 0; mf < 4; mf++) {
                const int r = wm * 64 + mf * 16 + gid;
                a[mf][0] = As[r    ][kb + qid];
                a[mf][1] = As[r + 8][kb + qid];
                a[mf][2] = As[r    ][kb + qid + 4];
                a[mf][3] = As[r + 8][kb + qid + 4];
            }
#pragma unroll
            for (int nf = 0; nf < 4; nf++) {
                const int r = wn * 32 + nf * 8 + gid;
                b[nf][0] = Bs[r][kb + qid];
                b[nf][1] = Bs[r][kb + qid + 4];
            }
#pragma unroll
            for (int mf = 0; mf < 4; mf++)
#pragma unroll
                for (int nf = 0; nf < 4; nf++) {
                    asm volatile(
                        "mma.sync.aligned.m16n8k8.row.col.f32.tf32.tf32.f32 "
                        "{%0,%1,%2,%3}, {%4,%5,%6,%7}, {%8,%9}, {%0,%1,%2,%3};"
                        : "+f"(acc[mf][nf][0]), "+f"(acc[mf][nf][1]),
                          "+f"(acc[mf][nf][2]), "+f"(acc[mf][nf][3])
                        : "r"(a[mf][0]), "r"(a[mf][1]), "r"(a[mf][2]), "r"(a[mf][3]),
                          "r"(b[nf][0]), "r"(b[nf][1]));
                }
        }
        __syncthreads();
    }

    // Epilogue: bias (+ RoPE on adjacent col pairs), float2 stores.
#pragma unroll
    for (int mf = 0; mf < 4; mf++) {
#pragma unroll
        for (int half = 0; half < 2; half++) {
            const int row = bm + wm * 64 + mf * 16 + gid + half * 8;
            const int s   = row & (S - 1);
#pragma unroll
            for (int nf = 0; nf < 4; nf++) {
                const int col = bn + wn * 32 + nf * 8 + 2 * qid;
                float v0 = acc[mf][nf][half * 2 + 0] + bias[col];
                float v1 = acc[mf][nf][half * 2 + 1] + bias[col + 1];
                if (ROPE) {
                    const int f = (col & (HD - 1)) >> 1;
                    const float cc = cosb[s * 64 + f], ss = sinb[s * 64 + f];
                    const float o0 = v0 * cc - v1 * ss;
                    const float o1 = v0 * ss + v1 * cc;
                    v0 = o0; v1 = o1;
                }
                *(float2*)(C + (size_t)row * DIM + col) = make_float2(v0, v1);
            }
        }
    }
}

// ---------------------------------------------------------------------------
// Flash attention (fp32). One block = (b, h, 64 q-rows). 64-key tiles.
// ---------------------------------------------------------------------------
constexpr int SMEM_ATTN = (128 * 68 * 2 + 64 * 132 + 64 * 68) * 4;  // 120832 B

__global__ __launch_bounds__(256)
void attn_kernel()
{
    extern __shared__ float sm[];
    float* Qs = sm;                  // [128 d][68]
    float* Ks = Qs + 128 * 68;       // [128 d][68]
    float* Vs = Ks + 128 * 68;       // [64 k][132]
    float* Ps = Vs + 64 * 132;       // [64 k][68]

    const int tid = threadIdx.x;
    const int tx = tid & 15, ty = tid >> 4;
    const int qb = blockIdx.x * 64;
    const int h  = blockIdx.y;
    const int b  = blockIdx.z;
    const size_t base = (size_t)b * S * DIM + (size_t)h * HD;

    for (int i = tid; i < 64 * 32; i += 256) {
        int qr = i >> 5;
        int d4 = (i & 31) << 2;
        float4 v = *(const float4*)(g_q + base + (size_t)(qb + qr) * DIM + d4);
        Qs[(d4 + 0) * 68 + qr] = v.x;
        Qs[(d4 + 1) * 68 + qr] = v.y;
        Qs[(d4 + 2) * 68 + qr] = v.z;
        Qs[(d4 + 3) * 68 + qr] = v.w;
    }

    float o[4][8];
#pragma unroll
    for (int i = 0; i < 4; i++)
#pragma unroll
        for (int j = 0; j < 8; j++) o[i][j] = 0.f;
    float rm[4], rl[4];
#pragma unroll
    for (int i = 0; i < 4; i++) { rm[i] = -1e30f; rl[i] = 0.f; }

    const int ntiles = (qb >> 6) + 1;
    for (int t = 0; t < ntiles; t++) {
        const int kb = t * 64;
        __syncthreads();
        for (int i = tid; i < 64 * 32; i += 256) {
            int kr = i >> 5;
            int d4 = (i & 31) << 2;
            float4 v = *(const float4*)(g_k + base + (size_t)(kb + kr) * DIM + d4);
            Ks[(d4 + 0) * 68 + kr] = v.x;
            Ks[(d4 + 1) * 68 + kr] = v.y;
            Ks[(d4 + 2) * 68 + kr] = v.z;
            Ks[(d4 + 3) * 68 + kr] = v.w;
            float4 w = *(const float4*)(g_v + base + (size_t)(kb + kr) * DIM + d4);
            *(float4*)(Vs + kr * 132 + d4) = w;
        }
        __syncthreads();

        float sc[4][4];
#pragma unroll
        for (int i = 0; i < 4; i++)
#pragma unroll
            for (int j = 0; j < 4; j++) sc[i][j] = 0.f;

        for (int d = 0; d < 128; d++) {
            float a[4], bb[4];
            *(float4*)a  = *(const float4*)(Qs + d * 68 + ty * 4);
            *(float4*)bb = *(const float4*)(Ks + d * 68 + tx * 4);
#pragma unroll
            for (int i = 0; i < 4; i++)
#pragma unroll
                for (int j = 0; j < 4; j++) sc[i][j] += a[i] * bb[j];
        }

        const bool diag = (t == ntiles - 1);
#pragma unroll
        for (int i = 0; i < 4; i++)
#pragma unroll
            for (int j = 0; j < 4; j++) {
                float s = sc[i][j] * SCALE;
                if (diag && (kb + tx * 4 + j > qb + ty * 4 + i)) s = -1e30f;
                sc[i][j] = s;
            }

#pragma unroll
        for (int i = 0; i < 4; i++) {
            float mloc = fmaxf(fmaxf(sc[i][0], sc[i][1]), fmaxf(sc[i][2], sc[i][3]));
#pragma unroll
            for (int off = 1; off < 16; off <<= 1)
                mloc = fmaxf(mloc, __shfl_xor_sync(0xffffffffu, mloc, off));
            const float newm = fmaxf(rm[i], mloc);
            const float corr = __expf(rm[i] - newm);
            rm[i] = newm;
            float p[4], psum = 0.f;
#pragma unroll
            for (int j = 0; j < 4; j++) { p[j] = __expf(sc[i][j] - newm); psum += p[j]; }
#pragma unroll
            for (int off = 1; off < 16; off <<= 1)
                psum += __shfl_xor_sync(0xffffffffu, psum, off);
            rl[i] = rl[i] * corr + psum;
#pragma unroll
            for (int j = 0; j < 8; j++) o[i][j] *= corr;
#pragma unroll
            for (int j = 0; j < 4; j++)
                Ps[(tx * 4 + j) * 68 + ty * 4 + i] = p[j];
        }
        __syncthreads();

        for (int kk = 0; kk < 64; kk++) {
            float a[4], bb[8];
            *(float4*)a        = *(const float4*)(Ps + kk * 68 + ty * 4);
            *(float4*)bb       = *(const float4*)(Vs + kk * 132 + tx * 4);
            *(float4*)(bb + 4) = *(const float4*)(Vs + kk * 132 + 64 + tx * 4);
#pragma unroll
            for (int i = 0; i < 4; i++)
#pragma unroll
                for (int j = 0; j < 8; j++) o[i][j] += a[i] * bb[j];
        }
    }

#pragma unroll
    for (int i = 0; i < 4; i++) {
        const float inv = 1.f / rl[i];
        const int q = qb + ty * 4 + i;
        float* dst = g_ctx + base + (size_t)q * DIM;
        *(float4*)(dst + tx * 4) =
            make_float4(o[i][0] * inv, o[i][1] * inv, o[i][2] * inv, o[i][3] * inv);
        *(float4*)(dst + 64 + tx * 4) =
            make_float4(o[i][4] * inv, o[i][5] * inv, o[i][6] * inv, o[i][7] * inv);
    }
}

// ---------------------------------------------------------------------------
// Launch
// ---------------------------------------------------------------------------
extern "C" void kernel_launch(void* const* d_in, const int* in_sizes, int n_in,
                              void* d_out, int out_size)
{
    const float* x    = (const float*)d_in[0];
    const float* cosb = (const float*)d_in[2];
    const float* sinb = (const float*)d_in[3];
    const float* wq   = (const float*)d_in[5];
    const float* bq   = (const float*)d_in[6];
    const float* wk   = (const float*)d_in[7];
    const float* bk   = (const float*)d_in[8];
    const float* wv   = (const float*)d_in[9];
    const float* bv   = (const float*)d_in[10];
    const float* wo   = (const float*)d_in[11];
    const float* bo   = (const float*)d_in[12];
    float* out = (float*)d_out;

    float *q, *k, *v, *ctx;
    cudaGetSymbolAddress((void**)&q,   g_q);
    cudaGetSymbolAddress((void**)&k,   g_k);
    cudaGetSymbolAddress((void**)&v,   g_v);
    cudaGetSymbolAddress((void**)&ctx, g_ctx);

    cudaFuncSetAttribute(attn_kernel,
                         cudaFuncAttributeMaxDynamicSharedMemorySize, SMEM_ATTN);

    dim3 gdim(DIM / 128, M / 128);   // (16, 32)
    gemm_tf32<1><<<gdim, 256>>>(x, wq, bq, cosb, sinb, q);
    gemm_tf32<1><<<gdim, 256>>>(x, wk, bk, cosb, sinb, k);
    gemm_tf32<0><<<gdim, 256>>>(x, wv, bv, cosb, sinb, v);

    dim3 adim(S / 64, H, B);         // (16, 16, 4)
    attn_kernel<<<adim, 256, SMEM_ATTN>>>();

    gemm_tf32<0><<<gdim, 256>>>(ctx, wo, bo, cosb, sinb, out);
}

// round 3
// speedup vs baseline: 3.0392x; 1.4630x over previous
#include <cuda_runtime.h>
#include <math.h>
#include <stdint.h>

// Problem constants
constexpr int B   = 4;
constexpr int S   = 1024;
constexpr int DIM = 2048;
constexpr int H   = 16;
constexpr int HD  = 128;
constexpr int M   = B * S;          // 4096 rows
constexpr float SCALE = 0.08838834764831845f;  // 1/sqrt(128)

// Scratch (allocation-free rule: __device__ globals)
__device__ float g_q[(size_t)M * DIM];
__device__ float g_k[(size_t)M * DIM];
__device__ float g_v[(size_t)M * DIM];
__device__ float g_ctx[(size_t)M * DIM];

__device__ __forceinline__ uint32_t f2tf32(float x) {
    uint32_t u;
    asm("cvt.rna.tf32.f32 %0, %1;" : "=r"(u) : "f"(x));
    return u;
}

__device__ __forceinline__ void mma_tf32(float* c, const uint32_t* a, const uint32_t* b) {
    asm volatile(
        "mma.sync.aligned.m16n8k8.row.col.f32.tf32.tf32.f32 "
        "{%0,%1,%2,%3}, {%4,%5,%6,%7}, {%8,%9}, {%0,%1,%2,%3};"
        : "+f"(c[0]), "+f"(c[1]), "+f"(c[2]), "+f"(c[3])
        : "r"(a[0]), "r"(a[1]), "r"(a[2]), "r"(a[3]), "r"(b[0]), "r"(b[1]));
}

// ---------------------------------------------------------------------------
// tf32 tensor-core GEMM: C[M,N] = A[M,K] @ W[N,K]^T + bias (+ fused RoPE).
// ---------------------------------------------------------------------------
template <int ROPE>
__global__ __launch_bounds__(256, 2)
void gemm_tf32(const float* __restrict__ A, const float* __restrict__ W,
               const float* __restrict__ bias,
               const float* __restrict__ cosb, const float* __restrict__ sinb,
               float* __restrict__ C)
{
    constexpr int K = DIM;
    __shared__ uint32_t As[128][36];
    __shared__ uint32_t Bs[128][36];

    const int tid  = threadIdx.x;
    const int warp = tid >> 5, lane = tid & 31;
    const int gid  = lane >> 2, qid = lane & 3;
    const int wm   = warp >> 2;
    const int wn   = warp & 3;
    const int bm   = blockIdx.y * 128, bn = blockIdx.x * 128;

    float acc[4][4][4];
#pragma unroll
    for (int i = 0; i < 4; i++)
#pragma unroll
        for (int j = 0; j < 4; j++)
#pragma unroll
            for (int c = 0; c < 4; c++) acc[i][j][c] = 0.f;

    for (int k0 = 0; k0 < K; k0 += 32) {
#pragma unroll
        for (int u = 0; u < 4; u++) {
            const int i   = tid + u * 256;
            const int row = i >> 3;
            const int kq  = (i & 7) << 2;
            float4 va = *(const float4*)(A + (size_t)(bm + row) * K + k0 + kq);
            As[row][kq + 0] = f2tf32(va.x);
            As[row][kq + 1] = f2tf32(va.y);
            As[row][kq + 2] = f2tf32(va.z);
            As[row][kq + 3] = f2tf32(va.w);
            float4 vb = *(const float4*)(W + (size_t)(bn + row) * K + k0 + kq);
            Bs[row][kq + 0] = f2tf32(vb.x);
            Bs[row][kq + 1] = f2tf32(vb.y);
            Bs[row][kq + 2] = f2tf32(vb.z);
            Bs[row][kq + 3] = f2tf32(vb.w);
        }
        __syncthreads();

#pragma unroll
        for (int ks = 0; ks < 4; ks++) {
            const int kb = ks * 8;
            uint32_t a[4][4], b[4][2];
#pragma unroll
            for (int mf = 0; mf < 4; mf++) {
                const int r = wm * 64 + mf * 16 + gid;
                a[mf][0] = As[r    ][kb + qid];
                a[mf][1] = As[r + 8][kb + qid];
                a[mf][2] = As[r    ][kb + qid + 4];
                a[mf][3] = As[r + 8][kb + qid + 4];
            }
#pragma unroll
            for (int nf = 0; nf < 4; nf++) {
                const int r = wn * 32 + nf * 8 + gid;
                b[nf][0] = Bs[r][kb + qid];
                b[nf][1] = Bs[r][kb + qid + 4];
            }
#pragma unroll
            for (int mf = 0; mf < 4; mf++)
#pragma unroll
                for (int nf = 0; nf < 4; nf++)
                    mma_tf32(acc[mf][nf], a[mf], b[nf]);
        }
        __syncthreads();
    }

#pragma unroll
    for (int mf = 0; mf < 4; mf++) {
#pragma unroll
        for (int half = 0; half < 2; half++) {
            const int row = bm + wm * 64 + mf * 16 + gid + half * 8;
            const int s   = row & (S - 1);
#pragma unroll
            for (int nf = 0; nf < 4; nf++) {
                const int col = bn + wn * 32 + nf * 8 + 2 * qid;
                float v0 = acc[mf][nf][half * 2 + 0] + bias[col];
                float v1 = acc[mf][nf][half * 2 + 1] + bias[col + 1];
                if (ROPE) {
                    const int f = (col & (HD - 1)) >> 1;
                    const float cc = cosb[s * 64 + f], ss = sinb[s * 64 + f];
                    const float o0 = v0 * cc - v1 * ss;
                    const float o1 = v0 * ss + v1 * cc;
                    v0 = o0; v1 = o1;
                }
                *(float2*)(C + (size_t)row * DIM + col) = make_float2(v0, v1);
            }
        }
    }
}

// ---------------------------------------------------------------------------
// Tensor-core flash attention (tf32 mma, fp32 softmax).
// Block = (b, h, 128 q-rows); 8 warps x 16 q; 64-key tiles.
// Computes S^T = K Q^T (no transposes needed), then O^T = V^T P.
// ---------------------------------------------------------------------------
constexpr int PADQ = 132, PADK = 132, PADV = 136, PADP = 24;
constexpr int SMEM_ATTN =
    (128 * PADQ + 64 * PADK + 64 * PADV + 8 * 64 * PADP) * 4;  // 185344 B

__global__ __launch_bounds__(256)
void attn_kernel()
{
    extern __shared__ uint32_t sm_u[];
    uint32_t* Qs = sm_u;                    // [128 q][132 d] tf32
    uint32_t* Ks = Qs + 128 * PADQ;         // [64 k][132 d]  tf32
    uint32_t* Vs = Ks + 64 * PADK;          // [64 k][136 d]  tf32
    uint32_t* Ps = Vs + 64 * PADV;          // 8 x [64 k][24 q] tf32

    const int tid  = threadIdx.x;
    const int warp = tid >> 5, lane = tid & 31;
    const int gid  = lane >> 2, qid = lane & 3;
    const int qb   = blockIdx.x * 128;
    const int h    = blockIdx.y;
    const int b    = blockIdx.z;
    const size_t base = (size_t)b * S * DIM + (size_t)h * HD;
    const int q0 = warp * 16;
    uint32_t* Pw = Ps + warp * 64 * PADP;

    // Stage Q tile (tf32)
    for (int i = tid; i < 128 * 32; i += 256) {
        const int row = i >> 5, d4 = (i & 31) << 2;
        float4 v = *(const float4*)(g_q + base + (size_t)(qb + row) * DIM + d4);
        *(uint4*)(Qs + row * PADQ + d4) =
            make_uint4(f2tf32(v.x), f2tf32(v.y), f2tf32(v.z), f2tf32(v.w));
    }

    // O^T accumulators: [d-frag 8][q-frag 2][4]; thread cols = 4 q values
    float oacc[8][2][4];
#pragma unroll
    for (int i = 0; i < 8; i++)
#pragma unroll
        for (int j = 0; j < 2; j++)
#pragma unroll
            for (int c = 0; c < 4; c++) oacc[i][j][c] = 0.f;
    float rm[4] = {-1e30f, -1e30f, -1e30f, -1e30f};
    float rl[4] = {0.f, 0.f, 0.f, 0.f};

    const int nt = qb / 64 + 2;
    for (int t = 0; t < nt; t++) {
        const int kb = t * 64;
        __syncthreads();
        for (int i = tid; i < 64 * 32; i += 256) {
            const int kr = i >> 5, d4 = (i & 31) << 2;
            float4 v = *(const float4*)(g_k + base + (size_t)(kb + kr) * DIM + d4);
            *(uint4*)(Ks + kr * PADK + d4) =
                make_uint4(f2tf32(v.x), f2tf32(v.y), f2tf32(v.z), f2tf32(v.w));
            float4 w = *(const float4*)(g_v + base + (size_t)(kb + kr) * DIM + d4);
            *(uint4*)(Vs + kr * PADV + d4) =
                make_uint4(f2tf32(w.x), f2tf32(w.y), f2tf32(w.z), f2tf32(w.w));
        }
        __syncthreads();

        if (kb <= qb + q0 + 15) {   // warp has at least one unmasked key
            // S^T = K @ Q^T : [64 key][16 q] per warp
            float sacc[4][2][4];
#pragma unroll
            for (int i = 0; i < 4; i++)
#pragma unroll
                for (int j = 0; j < 2; j++)
#pragma unroll
                    for (int c = 0; c < 4; c++) sacc[i][j][c] = 0.f;

#pragma unroll
            for (int kk = 0; kk < 128; kk += 8) {
                uint32_t a[4][4], bq[2][2];
#pragma unroll
                for (int mf = 0; mf < 4; mf++) {
                    const int r = mf * 16 + gid;
                    a[mf][0] = Ks[(r    ) * PADK + kk + qid];
                    a[mf][1] = Ks[(r + 8) * PADK + kk + qid];
                    a[mf][2] = Ks[(r    ) * PADK + kk + qid + 4];
                    a[mf][3] = Ks[(r + 8) * PADK + kk + qid + 4];
                }
#pragma unroll
                for (int nf = 0; nf < 2; nf++) {
                    const int r = q0 + nf * 8 + gid;
                    bq[nf][0] = Qs[r * PADQ + kk + qid];
                    bq[nf][1] = Qs[r * PADQ + kk + qid + 4];
                }
#pragma unroll
                for (int mf = 0; mf < 4; mf++)
#pragma unroll
                    for (int nf = 0; nf < 2; nf++)
                        mma_tf32(sacc[mf][nf], a[mf], bq[nf]);
            }

            // Scale + causal mask; per-column (q) online softmax.
            const bool diag = (kb + 63 > qb + q0);
            float mloc[4] = {-1e30f, -1e30f, -1e30f, -1e30f};
#pragma unroll
            for (int mf = 0; mf < 4; mf++)
#pragma unroll
                for (int nf = 0; nf < 2; nf++)
#pragma unroll
                    for (int ci = 0; ci < 4; ci++) {
                        float s = sacc[mf][nf][ci] * SCALE;
                        if (diag) {
                            const int key = kb + mf * 16 + gid + ((ci >> 1) << 3);
                            const int q   = qb + q0 + nf * 8 + 2 * qid + (ci & 1);
                            if (key > q) s = -1e30f;
                        }
                        sacc[mf][nf][ci] = s;
                        const int j = nf * 2 + (ci & 1);
                        mloc[j] = fmaxf(mloc[j], s);
                    }
#pragma unroll
            for (int j = 0; j < 4; j++) {
                mloc[j] = fmaxf(mloc[j], __shfl_xor_sync(0xffffffffu, mloc[j], 4));
                mloc[j] = fmaxf(mloc[j], __shfl_xor_sync(0xffffffffu, mloc[j], 8));
                mloc[j] = fmaxf(mloc[j], __shfl_xor_sync(0xffffffffu, mloc[j], 16));
            }
            float corr[4];
#pragma unroll
            for (int j = 0; j < 4; j++) {
                const float newm = fmaxf(rm[j], mloc[j]);
                corr[j] = __expf(rm[j] - newm);
                rm[j] = newm;
            }
            float psum[4] = {0.f, 0.f, 0.f, 0.f};
#pragma unroll
            for (int mf = 0; mf < 4; mf++)
#pragma unroll
                for (int nf = 0; nf < 2; nf++)
#pragma unroll
                    for (int ci = 0; ci < 4; ci++) {
                        const int j = nf * 2 + (ci & 1);
                        const float p = __expf(sacc[mf][nf][ci] - rm[j]);
                        psum[j] += p;
                        const int key = mf * 16 + gid + ((ci >> 1) << 3);
                        const int qq  = nf * 8 + 2 * qid + (ci & 1);
                        Pw[key * PADP + qq] = f2tf32(p);
                    }
#pragma unroll
            for (int j = 0; j < 4; j++) {
                psum[j] += __shfl_xor_sync(0xffffffffu, psum[j], 4);
                psum[j] += __shfl_xor_sync(0xffffffffu, psum[j], 8);
                psum[j] += __shfl_xor_sync(0xffffffffu, psum[j], 16);
                rl[j] = rl[j] * corr[j] + psum[j];
            }
            // Rescale output accumulators
#pragma unroll
            for (int mfo = 0; mfo < 8; mfo++)
#pragma unroll
                for (int nf = 0; nf < 2; nf++)
#pragma unroll
                    for (int ci = 0; ci < 4; ci++)
                        oacc[mfo][nf][ci] *= corr[nf * 2 + (ci & 1)];

            __syncwarp();

            // O^T += V^T @ P : A = V^T (from row-major Vs), B = P^T (Pw)
#pragma unroll
            for (int ks = 0; ks < 8; ks++) {
                uint32_t bp[2][2];
#pragma unroll
                for (int nf = 0; nf < 2; nf++) {
                    bp[nf][0] = Pw[(ks * 8 + qid    ) * PADP + nf * 8 + gid];
                    bp[nf][1] = Pw[(ks * 8 + qid + 4) * PADP + nf * 8 + gid];
                }
#pragma unroll
                for (int mfo = 0; mfo < 8; mfo++) {
                    uint32_t a[4];
                    a[0] = Vs[(ks * 8 + qid    ) * PADV + mfo * 16 + gid];
                    a[1] = Vs[(ks * 8 + qid    ) * PADV + mfo * 16 + gid + 8];
                    a[2] = Vs[(ks * 8 + qid + 4) * PADV + mfo * 16 + gid];
                    a[3] = Vs[(ks * 8 + qid + 4) * PADV + mfo * 16 + gid + 8];
#pragma unroll
                    for (int nf = 0; nf < 2; nf++)
                        mma_tf32(oacc[mfo][nf], a, bp[nf]);
                }
            }
        }
    }

    // Epilogue: normalize, write ctx[b][q][h*HD + d]
    float inv[4];
#pragma unroll
    for (int j = 0; j < 4; j++) inv[j] = 1.f / rl[j];
#pragma unroll
    for (int mfo = 0; mfo < 8; mfo++)
#pragma unroll
        for (int nf = 0; nf < 2; nf++)
#pragma unroll
            for (int ci = 0; ci < 4; ci++) {
                const int d = mfo * 16 + gid + ((ci >> 1) << 3);
                const int q = qb + q0 + nf * 8 + 2 * qid + (ci & 1);
                g_ctx[base + (size_t)q * DIM + d] =
                    oacc[mfo][nf][ci] * inv[nf * 2 + (ci & 1)];
            }
}

// ---------------------------------------------------------------------------
// Launch
// ---------------------------------------------------------------------------
extern "C" void kernel_launch(void* const* d_in, const int* in_sizes, int n_in,
                              void* d_out, int out_size)
{
    const float* x    = (const float*)d_in[0];
    const float* cosb = (const float*)d_in[2];
    const float* sinb = (const float*)d_in[3];
    const float* wq   = (const float*)d_in[5];
    const float* bq   = (const float*)d_in[6];
    const float* wk   = (const float*)d_in[7];
    const float* bk   = (const float*)d_in[8];
    const float* wv   = (const float*)d_in[9];
    const float* bv   = (const float*)d_in[10];
    const float* wo   = (const float*)d_in[11];
    const float* bo   = (const float*)d_in[12];
    float* out = (float*)d_out;

    float *q, *k, *v, *ctx;
    cudaGetSymbolAddress((void**)&q,   g_q);
    cudaGetSymbolAddress((void**)&k,   g_k);
    cudaGetSymbolAddress((void**)&v,   g_v);
    cudaGetSymbolAddress((void**)&ctx, g_ctx);

    cudaFuncSetAttribute(attn_kernel,
                         cudaFuncAttributeMaxDynamicSharedMemorySize, SMEM_ATTN);

    dim3 gdim(DIM / 128, M / 128);   // (16, 32)
    gemm_tf32<1><<<gdim, 256>>>(x, wq, bq, cosb, sinb, q);
    gemm_tf32<1><<<gdim, 256>>>(x, wk, bk, cosb, sinb, k);
    gemm_tf32<0><<<gdim, 256>>>(x, wv, bv, cosb, sinb, v);

    dim3 adim(S / 128, H, B);        // (8, 16, 4)
    attn_kernel<<<adim, 256, SMEM_ATTN>>>();

    gemm_tf32<0><<<gdim, 256>>>(ctx, wo, bo, cosb, sinb, out);
}

// round 4
// speedup vs baseline: 3.4495x; 1.1350x over previous
#include <cuda_runtime.h>
#include <math.h>
#include <stdint.h>

// Problem constants
constexpr int B   = 4;
constexpr int S   = 1024;
constexpr int DIM = 2048;
constexpr int H   = 16;
constexpr int HD  = 128;
constexpr int M   = B * S;          // 4096 rows
constexpr float SCALE = 0.08838834764831845f;  // 1/sqrt(128)

// Scratch (allocation-free rule: __device__ globals). tf32 bit patterns.
__device__ uint32_t g_q[(size_t)M * DIM];
__device__ uint32_t g_k[(size_t)M * DIM];
__device__ uint32_t g_v[(size_t)M * DIM];
__device__ uint32_t g_ctx[(size_t)M * DIM];
__device__ uint32_t c_x [(size_t)M * DIM];
__device__ uint32_t c_wq[(size_t)DIM * DIM];
__device__ uint32_t c_wk[(size_t)DIM * DIM];
__device__ uint32_t c_wv[(size_t)DIM * DIM];
__device__ uint32_t c_wo[(size_t)DIM * DIM];

__device__ __forceinline__ uint32_t f2tf32(float x) {
    uint32_t u;
    asm("cvt.rna.tf32.f32 %0, %1;" : "=r"(u) : "f"(x));
    return u;
}

__device__ __forceinline__ void mma_tf32(float* c, const uint32_t* a, const uint32_t* b) {
    asm volatile(
        "mma.sync.aligned.m16n8k8.row.col.f32.tf32.tf32.f32 "
        "{%0,%1,%2,%3}, {%4,%5,%6,%7}, {%8,%9}, {%0,%1,%2,%3};"
        : "+f"(c[0]), "+f"(c[1]), "+f"(c[2]), "+f"(c[3])
        : "r"(a[0]), "r"(a[1]), "r"(a[2]), "r"(a[3]), "r"(b[0]), "r"(b[1]));
}

__device__ __forceinline__ void cp16(uint32_t dst, const void* src) {
    asm volatile("cp.async.cg.shared.global [%0], [%1], 16;" :: "r"(dst), "l"(src));
}

// ---------------------------------------------------------------------------
// Elementwise fp32 -> tf32 bit conversion
// ---------------------------------------------------------------------------
__global__ void cvt_kernel(const float4* __restrict__ in, uint4* __restrict__ out, int n4)
{
    const int i = blockIdx.x * blockDim.x + threadIdx.x;
    if (i < n4) {
        float4 v = in[i];
        out[i] = make_uint4(f2tf32(v.x), f2tf32(v.y), f2tf32(v.z), f2tf32(v.w));
    }
}

// ---------------------------------------------------------------------------
// tf32 tensor-core GEMM, cp.async double-buffered.
// C[M,N] = A[M,K] @ W[N,K]^T + bias, optional fused RoPE.
// QKV=1: blockIdx.z selects {q,k,v}; RoPE for z<2; output = tf32 bits.
// QKV=0: single output projection; output = fp32.
// ---------------------------------------------------------------------------
constexpr int GP   = 36;                       // padded row (144B, 16B aligned)
constexpr int ASZ  = 128 * GP;                 // u32 per array per stage
constexpr int SMEM_GEMM = 4 * ASZ * 4;         // 73728 B

template <int QKV>
__global__ __launch_bounds__(256, 2)
void gemm_tf32(const uint32_t* __restrict__ A,
               const uint32_t* __restrict__ W0, const uint32_t* __restrict__ W1,
               const uint32_t* __restrict__ W2,
               const float* __restrict__ b0, const float* __restrict__ b1,
               const float* __restrict__ b2,
               void* __restrict__ C0, void* __restrict__ C1, void* __restrict__ C2,
               const float* __restrict__ cosb, const float* __restrict__ sinb)
{
    constexpr int K = DIM;
    extern __shared__ uint32_t sm[];

    const int z = QKV ? blockIdx.z : 0;
    const uint32_t* W  = (z == 0) ? W0 : (z == 1) ? W1 : W2;
    const float* bias  = (z == 0) ? b0 : (z == 1) ? b1 : b2;
    void* C            = (z == 0) ? C0 : (z == 1) ? C1 : C2;
    const bool rope    = QKV && (z < 2);

    const int tid  = threadIdx.x;
    const int warp = tid >> 5, lane = tid & 31;
    const int gid  = lane >> 2, qid = lane & 3;
    const int wm   = warp >> 2;
    const int wn   = warp & 3;
    const int bm   = blockIdx.y * 128, bn = blockIdx.x * 128;

    const int prow = tid >> 3;            // 0..31 base row (x4 per u)
    const int pkq  = (tid & 7) << 2;      // 0,4,...,28

    float acc[4][4][4];
#pragma unroll
    for (int i = 0; i < 4; i++)
#pragma unroll
        for (int j = 0; j < 4; j++)
#pragma unroll
            for (int c = 0; c < 4; c++) acc[i][j][c] = 0.f;

    auto prefetch = [&](int k0, int stage) {
        uint32_t* As = sm + stage * 2 * ASZ;
        uint32_t* Bs = As + ASZ;
        const uint32_t as_b = (uint32_t)__cvta_generic_to_shared(As);
        const uint32_t bs_b = (uint32_t)__cvta_generic_to_shared(Bs);
#pragma unroll
        for (int u = 0; u < 4; u++) {
            const int row = prow + u * 32;
            cp16(as_b + (row * GP + pkq) * 4, A + (size_t)(bm + row) * K + k0 + pkq);
            cp16(bs_b + (row * GP + pkq) * 4, W + (size_t)(bn + row) * K + k0 + pkq);
        }
    };

    int stage = 0;
    prefetch(0, 0);
    asm volatile("cp.async.commit_group;");

    for (int k0 = 0; k0 < K; k0 += 32) {
        const bool more = (k0 + 32 < K);
        if (more) {
            prefetch(k0 + 32, stage ^ 1);
            asm volatile("cp.async.commit_group;");
            asm volatile("cp.async.wait_group 1;");
        } else {
            asm volatile("cp.async.wait_group 0;");
        }
        __syncthreads();

        const uint32_t* As = sm + stage * 2 * ASZ;
        const uint32_t* Bs = As + ASZ;
#pragma unroll
        for (int ks = 0; ks < 4; ks++) {
            const int kb = ks * 8;
            uint32_t a[4][4], b[4][2];
#pragma unroll
            for (int mf = 0; mf < 4; mf++) {
                const int r = wm * 64 + mf * 16 + gid;
                a[mf][0] = As[(r    ) * GP + kb + qid];
                a[mf][1] = As[(r + 8) * GP + kb + qid];
                a[mf][2] = As[(r    ) * GP + kb + qid + 4];
                a[mf][3] = As[(r + 8) * GP + kb + qid + 4];
            }
#pragma unroll
            for (int nf = 0; nf < 4; nf++) {
                const int r = wn * 32 + nf * 8 + gid;
                b[nf][0] = Bs[r * GP + kb + qid];
                b[nf][1] = Bs[r * GP + kb + qid + 4];
            }
#pragma unroll
            for (int mf = 0; mf < 4; mf++)
#pragma unroll
                for (int nf = 0; nf < 4; nf++)
                    mma_tf32(acc[mf][nf], a[mf], b[nf]);
        }
        __syncthreads();
        stage ^= 1;
    }

    // Epilogue: bias (+ RoPE on adjacent col pairs).
#pragma unroll
    for (int mf = 0; mf < 4; mf++) {
#pragma unroll
        for (int half = 0; half < 2; half++) {
            const int row = bm + wm * 64 + mf * 16 + gid + half * 8;
            const int s   = row & (S - 1);
#pragma unroll
            for (int nf = 0; nf < 4; nf++) {
                const int col = bn + wn * 32 + nf * 8 + 2 * qid;
                float v0 = acc[mf][nf][half * 2 + 0] + bias[col];
                float v1 = acc[mf][nf][half * 2 + 1] + bias[col + 1];
                if (rope) {
                    const int f = (col & (HD - 1)) >> 1;
                    const float cc = cosb[s * 64 + f], ss = sinb[s * 64 + f];
                    const float o0 = v0 * cc - v1 * ss;
                    const float o1 = v0 * ss + v1 * cc;
                    v0 = o0; v1 = o1;
                }
                if (QKV)
                    *(uint2*)((uint32_t*)C + (size_t)row * DIM + col) =
                        make_uint2(f2tf32(v0), f2tf32(v1));
                else
                    *(float2*)((float*)C + (size_t)row * DIM + col) =
                        make_float2(v0, v1);
            }
        }
    }
}

// ---------------------------------------------------------------------------
// Tensor-core flash attention (tf32 mma, fp32 softmax).
// Block = (b, h, 128 q-rows); 8 warps x 16 q; 64-key tiles.
// ---------------------------------------------------------------------------
constexpr int PADQ = 132, PADK = 132, PADV = 136, PADP = 24;
constexpr int SMEM_ATTN =
    (128 * PADQ + 64 * PADK + 64 * PADV + 8 * 64 * PADP) * 4;  // 185344 B

__global__ __launch_bounds__(256)
void attn_kernel()
{
    extern __shared__ uint32_t sm_u[];
    uint32_t* Qs = sm_u;
    uint32_t* Ks = Qs + 128 * PADQ;
    uint32_t* Vs = Ks + 64 * PADK;
    uint32_t* Ps = Vs + 64 * PADV;

    const int tid  = threadIdx.x;
    const int warp = tid >> 5, lane = tid & 31;
    const int gid  = lane >> 2, qid = lane & 3;
    const int qb   = blockIdx.x * 128;
    const int h    = blockIdx.y;
    const int b    = blockIdx.z;
    const size_t base = (size_t)b * S * DIM + (size_t)h * HD;
    const int q0 = warp * 16;
    uint32_t* Pw = Ps + warp * 64 * PADP;

    for (int i = tid; i < 128 * 32; i += 256) {
        const int row = i >> 5, d4 = (i & 31) << 2;
        *(uint4*)(Qs + row * PADQ + d4) =
            *(const uint4*)(g_q + base + (size_t)(qb + row) * DIM + d4);
    }

    float oacc[8][2][4];
#pragma unroll
    for (int i = 0; i < 8; i++)
#pragma unroll
        for (int j = 0; j < 2; j++)
#pragma unroll
            for (int c = 0; c < 4; c++) oacc[i][j][c] = 0.f;
    float rm[4] = {-1e30f, -1e30f, -1e30f, -1e30f};
    float rl[4] = {0.f, 0.f, 0.f, 0.f};

    const int nt = qb / 64 + 2;
    for (int t = 0; t < nt; t++) {
        const int kb = t * 64;
        __syncthreads();
        for (int i = tid; i < 64 * 32; i += 256) {
            const int kr = i >> 5, d4 = (i & 31) << 2;
            *(uint4*)(Ks + kr * PADK + d4) =
                *(const uint4*)(g_k + base + (size_t)(kb + kr) * DIM + d4);
            *(uint4*)(Vs + kr * PADV + d4) =
                *(const uint4*)(g_v + base + (size_t)(kb + kr) * DIM + d4);
        }
        __syncthreads();

        if (kb <= qb + q0 + 15) {
            float sacc[4][2][4];
#pragma unroll
            for (int i = 0; i < 4; i++)
#pragma unroll
                for (int j = 0; j < 2; j++)
#pragma unroll
                    for (int c = 0; c < 4; c++) sacc[i][j][c] = 0.f;

#pragma unroll
            for (int kk = 0; kk < 128; kk += 8) {
                uint32_t a[4][4], bq[2][2];
#pragma unroll
                for (int mf = 0; mf < 4; mf++) {
                    const int r = mf * 16 + gid;
                    a[mf][0] = Ks[(r    ) * PADK + kk + qid];
                    a[mf][1] = Ks[(r + 8) * PADK + kk + qid];
                    a[mf][2] = Ks[(r    ) * PADK + kk + qid + 4];
                    a[mf][3] = Ks[(r + 8) * PADK + kk + qid + 4];
                }
#pragma unroll
                for (int nf = 0; nf < 2; nf++) {
                    const int r = q0 + nf * 8 + gid;
                    bq[nf][0] = Qs[r * PADQ + kk + qid];
                    bq[nf][1] = Qs[r * PADQ + kk + qid + 4];
                }
#pragma unroll
                for (int mf = 0; mf < 4; mf++)
#pragma unroll
                    for (int nf = 0; nf < 2; nf++)
                        mma_tf32(sacc[mf][nf], a[mf], bq[nf]);
            }

            const bool diag = (kb + 63 > qb + q0);
            float mloc[4] = {-1e30f, -1e30f, -1e30f, -1e30f};
#pragma unroll
            for (int mf = 0; mf < 4; mf++)
#pragma unroll
                for (int nf = 0; nf < 2; nf++)
#pragma unroll
                    for (int ci = 0; ci < 4; ci++) {
                        float s = sacc[mf][nf][ci] * SCALE;
                        if (diag) {
                            const int key = kb + mf * 16 + gid + ((ci >> 1) << 3);
                            const int q   = qb + q0 + nf * 8 + 2 * qid + (ci & 1);
                            if (key > q) s = -1e30f;
                        }
                        sacc[mf][nf][ci] = s;
                        const int j = nf * 2 + (ci & 1);
                        mloc[j] = fmaxf(mloc[j], s);
                    }
#pragma unroll
            for (int j = 0; j < 4; j++) {
                mloc[j] = fmaxf(mloc[j], __shfl_xor_sync(0xffffffffu, mloc[j], 4));
                mloc[j] = fmaxf(mloc[j], __shfl_xor_sync(0xffffffffu, mloc[j], 8));
                mloc[j] = fmaxf(mloc[j], __shfl_xor_sync(0xffffffffu, mloc[j], 16));
            }
            float corr[4];
#pragma unroll
            for (int j = 0; j < 4; j++) {
                const float newm = fmaxf(rm[j], mloc[j]);
                corr[j] = __expf(rm[j] - newm);
                rm[j] = newm;
            }
            float psum[4] = {0.f, 0.f, 0.f, 0.f};
#pragma unroll
            for (int mf = 0; mf < 4; mf++)
#pragma unroll
                for (int nf = 0; nf < 2; nf++)
#pragma unroll
                    for (int ci = 0; ci < 4; ci++) {
                        const int j = nf * 2 + (ci & 1);
                        const float p = __expf(sacc[mf][nf][ci] - rm[j]);
                        psum[j] += p;
                        const int key = mf * 16 + gid + ((ci >> 1) << 3);
                        const int qq  = nf * 8 + 2 * qid + (ci & 1);
                        Pw[key * PADP + qq] = f2tf32(p);
                    }
#pragma unroll
            for (int j = 0; j < 4; j++) {
                psum[j] += __shfl_xor_sync(0xffffffffu, psum[j], 4);
                psum[j] += __shfl_xor_sync(0xffffffffu, psum[j], 8);
                psum[j] += __shfl_xor_sync(0xffffffffu, psum[j], 16);
                rl[j] = rl[j] * corr[j] + psum[j];
            }
#pragma unroll
            for (int mfo = 0; mfo < 8; mfo++)
#pragma unroll
                for (int nf = 0; nf < 2; nf++)
#pragma unroll
                    for (int ci = 0; ci < 4; ci++)
                        oacc[mfo][nf][ci] *= corr[nf * 2 + (ci & 1)];

            __syncwarp();

#pragma unroll
            for (int ks = 0; ks < 8; ks++) {
                uint32_t bp[2][2];
#pragma unroll
                for (int nf = 0; nf < 2; nf++) {
                    bp[nf][0] = Pw[(ks * 8 + qid    ) * PADP + nf * 8 + gid];
                    bp[nf][1] = Pw[(ks * 8 + qid + 4) * PADP + nf * 8 + gid];
                }
#pragma unroll
                for (int mfo = 0; mfo < 8; mfo++) {
                    uint32_t a[4];
                    a[0] = Vs[(ks * 8 + qid    ) * PADV + mfo * 16 + gid];
                    a[1] = Vs[(ks * 8 + qid    ) * PADV + mfo * 16 + gid + 8];
                    a[2] = Vs[(ks * 8 + qid + 4) * PADV + mfo * 16 + gid];
                    a[3] = Vs[(ks * 8 + qid + 4) * PADV + mfo * 16 + gid + 8];
#pragma unroll
                    for (int nf = 0; nf < 2; nf++)
                        mma_tf32(oacc[mfo][nf], a, bp[nf]);
                }
            }
        }
    }

    float inv[4];
#pragma unroll
    for (int j = 0; j < 4; j++) inv[j] = 1.f / rl[j];
#pragma unroll
    for (int mfo = 0; mfo < 8; mfo++)
#pragma unroll
        for (int nf = 0; nf < 2; nf++)
#pragma unroll
            for (int ci = 0; ci < 4; ci++) {
                const int d = mfo * 16 + gid + ((ci >> 1) << 3);
                const int q = qb + q0 + nf * 8 + 2 * qid + (ci & 1);
                g_ctx[base + (size_t)q * DIM + d] =
                    f2tf32(oacc[mfo][nf][ci] * inv[nf * 2 + (ci & 1)]);
            }
}

// ---------------------------------------------------------------------------
// Launch
// ---------------------------------------------------------------------------
extern "C" void kernel_launch(void* const* d_in, const int* in_sizes, int n_in,
                              void* d_out, int out_size)
{
    const float* x    = (const float*)d_in[0];
    const float* cosb = (const float*)d_in[2];
    const float* sinb = (const float*)d_in[3];
    const float* wq   = (const float*)d_in[5];
    const float* bq   = (const float*)d_in[6];
    const float* wk   = (const float*)d_in[7];
    const float* bk   = (const float*)d_in[8];
    const float* wv   = (const float*)d_in[9];
    const float* bv   = (const float*)d_in[10];
    const float* wo   = (const float*)d_in[11];
    const float* bo   = (const float*)d_in[12];
    float* out = (float*)d_out;

    uint32_t *q, *k, *v, *ctx, *cx, *cwq, *cwk, *cwv, *cwo;
    cudaGetSymbolAddress((void**)&q,   g_q);
    cudaGetSymbolAddress((void**)&k,   g_k);
    cudaGetSymbolAddress((void**)&v,   g_v);
    cudaGetSymbolAddress((void**)&ctx, g_ctx);
    cudaGetSymbolAddress((void**)&cx,  c_x);
    cudaGetSymbolAddress((void**)&cwq, c_wq);
    cudaGetSymbolAddress((void**)&cwk, c_wk);
    cudaGetSymbolAddress((void**)&cwv, c_wv);
    cudaGetSymbolAddress((void**)&cwo, c_wo);

    cudaFuncSetAttribute(attn_kernel,
                         cudaFuncAttributeMaxDynamicSharedMemorySize, SMEM_ATTN);
    cudaFuncSetAttribute(gemm_tf32<1>,
                         cudaFuncAttributeMaxDynamicSharedMemorySize, SMEM_GEMM);
    cudaFuncSetAttribute(gemm_tf32<0>,
                         cudaFuncAttributeMaxDynamicSharedMemorySize, SMEM_GEMM);

    // fp32 -> tf32 pre-conversion
    const int nx4 = M * DIM / 4, nw4 = DIM * DIM / 4;
    cvt_kernel<<<(nx4 + 255) / 256, 256>>>((const float4*)x,  (uint4*)cx,  nx4);
    cvt_kernel<<<(nw4 + 255) / 256, 256>>>((const float4*)wq, (uint4*)cwq, nw4);
    cvt_kernel<<<(nw4 + 255) / 256, 256>>>((const float4*)wk, (uint4*)cwk, nw4);
    cvt_kernel<<<(nw4 + 255) / 256, 256>>>((const float4*)wv, (uint4*)cwv, nw4);
    cvt_kernel<<<(nw4 + 255) / 256, 256>>>((const float4*)wo, (uint4*)cwo, nw4);

    // Fused QKV projections (+bias, +RoPE for q/k)
    dim3 gqkv(DIM / 128, M / 128, 3);   // (16, 32, 3)
    gemm_tf32<1><<<gqkv, 256, SMEM_GEMM>>>(cx, cwq, cwk, cwv, bq, bk, bv,
                                           q, k, v, cosb, sinb);

    dim3 adim(S / 128, H, B);           // (8, 16, 4)
    attn_kernel<<<adim, 256, SMEM_ATTN>>>();

    dim3 gdim(DIM / 128, M / 128, 1);
    gemm_tf32<0><<<gdim, 256, SMEM_GEMM>>>(ctx, cwo, cwo, cwo, bo, bo, bo,
                                           out, out, out, cosb, sinb);
}

// round 7
// speedup vs baseline: 6.4391x; 1.8667x over previous
#include <cuda_runtime.h>
#include <cuda_fp16.h>
#include <math.h>
#include <stdint.h>

// Problem constants
constexpr int B   = 4;
constexpr int S   = 1024;
constexpr int DIM = 2048;
constexpr int H   = 16;
constexpr int HD  = 128;
constexpr int M   = B * S;          // 4096 rows
constexpr float SCALE = 0.08838834764831845f;  // 1/sqrt(128)

// Scratch (allocation-free rule: __device__ globals), fp16.
__device__ __half g_q  [(size_t)M * DIM];
__device__ __half g_k  [(size_t)M * DIM];
__device__ __half g_vt [(size_t)M * DIM];   // transposed: [(b*H+h)*HD+d][s]
__device__ __half g_ctx[(size_t)M * DIM];
__device__ __half c_x  [(size_t)M * DIM];
__device__ __half c_wq [(size_t)DIM * DIM];
__device__ __half c_wk [(size_t)DIM * DIM];
__device__ __half c_wv [(size_t)DIM * DIM];
__device__ __half c_wo [(size_t)DIM * DIM];

__device__ __forceinline__ void mma_f16(float* c, const uint32_t* a, const uint32_t* b) {
    asm volatile(
        "mma.sync.aligned.m16n8k16.row.col.f32.f16.f16.f32 "
        "{%0,%1,%2,%3}, {%4,%5,%6,%7}, {%8,%9}, {%0,%1,%2,%3};"
        : "+f"(c[0]), "+f"(c[1]), "+f"(c[2]), "+f"(c[3])
        : "r"(a[0]), "r"(a[1]), "r"(a[2]), "r"(a[3]), "r"(b[0]), "r"(b[1]));
}

__device__ __forceinline__ void cp16(uint32_t dst, const void* src) {
    asm volatile("cp.async.cg.shared.global [%0], [%1], 16;" :: "r"(dst), "l"(src));
}

// ---------------------------------------------------------------------------
// Elementwise fp32 -> fp16 conversion
// ---------------------------------------------------------------------------
__global__ void cvt_kernel(const float4* __restrict__ in, __half2* __restrict__ out, int n4)
{
    const int i = blockIdx.x * blockDim.x + threadIdx.x;
    if (i < n4) {
        float4 v = in[i];
        out[2 * i]     = __floats2half2_rn(v.x, v.y);
        out[2 * i + 1] = __floats2half2_rn(v.z, v.w);
    }
}

// ---------------------------------------------------------------------------
// fp16 tensor-core GEMM: C[M,N] = A[M,K] @ W[N,K]^T + bias (+ fused RoPE).
// 128x128 tile, BK=64, double-buffered cp.async, m16n8k16, 8 warps (2x4).
// QKV=1: z selects {q,k,v}; RoPE for z<2; q/k stored normal fp16, v transposed.
// QKV=0: output projection -> fp32.
// ---------------------------------------------------------------------------
constexpr int GROW   = 72;                   // halfs per padded row (144 B)
constexpr int ASTAGE = 128 * GROW;           // halfs per array per stage
constexpr int SMEM_GEMM = 2 * 2 * ASTAGE * 2;  // 73728 B

template <int QKV>
__global__ __launch_bounds__(256, 2)
void gemm_f16(const __half* __restrict__ A,
              const __half* __restrict__ W0, const __half* __restrict__ W1,
              const __half* __restrict__ W2,
              const float* __restrict__ b0, const float* __restrict__ b1,
              const float* __restrict__ b2,
              void* __restrict__ C0, void* __restrict__ C1, void* __restrict__ C2,
              const float* __restrict__ cosb, const float* __restrict__ sinb)
{
    constexpr int K = DIM;
    extern __shared__ __half smh[];

    const int z = QKV ? blockIdx.z : 0;
    const __half* W   = (z == 0) ? W0 : (z == 1) ? W1 : W2;
    const float* bias = (z == 0) ? b0 : (z == 1) ? b1 : b2;
    void* C           = (z == 0) ? C0 : (z == 1) ? C1 : C2;
    const bool rope   = QKV && (z < 2);

    const int tid  = threadIdx.x;
    const int warp = tid >> 5, lane = tid & 31;
    const int gid  = lane >> 2, qid = lane & 3;
    const int wm   = warp >> 2, wn = warp & 3;
    const int bm   = blockIdx.y * 128, bn = blockIdx.x * 128;
    const uint32_t sbase = (uint32_t)__cvta_generic_to_shared(smh);

    float acc[4][4][4];
#pragma unroll
    for (int i = 0; i < 4; i++)
#pragma unroll
        for (int j = 0; j < 4; j++)
#pragma unroll
            for (int c = 0; c < 4; c++) acc[i][j][c] = 0.f;

    auto prefetch = [&](int k0, int st) {
        const uint32_t ab = sbase + st * 2 * ASTAGE * 2;
        const uint32_t bb = ab + ASTAGE * 2;
#pragma unroll
        for (int i = 0; i < 4; i++) {
            const int c = tid + i * 256;        // 0..1023
            const int row = c >> 3, ch = c & 7; // 128 rows x 8 chunks (16B)
            cp16(ab + row * 144 + ch * 16, A + (size_t)(bm + row) * K + k0 + ch * 8);
            cp16(bb + row * 144 + ch * 16, W + (size_t)(bn + row) * K + k0 + ch * 8);
        }
        asm volatile("cp.async.commit_group;");
    };

    prefetch(0, 0);
    for (int slab = 0; slab < K / 64; slab++) {
        const int st = slab & 1;
        if (slab + 1 < K / 64) {
            prefetch(slab * 64 + 64, st ^ 1);
            asm volatile("cp.async.wait_group 1;" ::: "memory");
        } else {
            asm volatile("cp.async.wait_group 0;" ::: "memory");
        }
        __syncthreads();

        const uint32_t* As32 = (const uint32_t*)(smh + st * 2 * ASTAGE);
        const uint32_t* Bs32 = As32 + ASTAGE / 2;
#pragma unroll
        for (int ks = 0; ks < 4; ks++) {
            const int kw = ks * 8 + qid;
            uint32_t a[4][4], b[4][2];
#pragma unroll
            for (int mf = 0; mf < 4; mf++) {
                const int r = wm * 64 + mf * 16 + gid;
                a[mf][0] = As32[(r    ) * 36 + kw];
                a[mf][1] = As32[(r + 8) * 36 + kw];
                a[mf][2] = As32[(r    ) * 36 + kw + 4];
                a[mf][3] = As32[(r + 8) * 36 + kw + 4];
            }
#pragma unroll
            for (int nf = 0; nf < 4; nf++) {
                const int r = wn * 32 + nf * 8 + gid;
                b[nf][0] = Bs32[r * 36 + kw];
                b[nf][1] = Bs32[r * 36 + kw + 4];
            }
#pragma unroll
            for (int mf = 0; mf < 4; mf++)
#pragma unroll
                for (int nf = 0; nf < 4; nf++)
                    mma_f16(acc[mf][nf], a[mf], b[nf]);
        }
        __syncthreads();
    }

    // Epilogue: bias (+ RoPE on adjacent column pairs).
#pragma unroll
    for (int mf = 0; mf < 4; mf++) {
#pragma unroll
        for (int hf = 0; hf < 2; hf++) {
            const int row = bm + wm * 64 + mf * 16 + gid + hf * 8;
            const int s   = row & (S - 1);
#pragma unroll
            for (int nf = 0; nf < 4; nf++) {
                const int col = bn + wn * 32 + nf * 8 + 2 * qid;
                float v0 = acc[mf][nf][hf * 2 + 0] + bias[col];
                float v1 = acc[mf][nf][hf * 2 + 1] + bias[col + 1];
                if (rope) {
                    const int f = (col & (HD - 1)) >> 1;
                    const float cc = cosb[s * 64 + f], ss = sinb[s * 64 + f];
                    const float o0 = v0 * cc - v1 * ss;
                    const float o1 = v0 * ss + v1 * cc;
                    v0 = o0; v1 = o1;
                }
                if (QKV) {
                    if (z == 2) {
                        // transposed store: v_t[(b*H+h)*HD+d][s]
                        const int bb2 = row >> 10, sp = row & 1023;
                        const int hh = col >> 7, dd = col & 127;
                        __half* vt = (__half*)C;
                        vt[((size_t)((bb2 * H + hh) * HD + dd)) * S + sp] =
                            __float2half(v0);
                        vt[((size_t)((bb2 * H + hh) * HD + dd + 1)) * S + sp] =
                            __float2half(v1);
                    } else {
                        *(__half2*)((__half*)C + (size_t)row * DIM + col) =
                            __floats2half2_rn(v0, v1);
                    }
                } else {
                    *(float2*)((float*)C + (size_t)row * DIM + col) =
                        make_float2(v0, v1);
                }
            }
        }
    }
}

// ---------------------------------------------------------------------------
// fp16 tensor-core flash attention (fp32 softmax/accum).
// Block = (b, h, 128 q); 8 warps x 16 q; 64-key tiles, cp.async double buffer.
// S^T = K Q^T, then O^T = V^T P (V pre-transposed in gmem).
// ---------------------------------------------------------------------------
constexpr int QROW = 136, KROW = 136, VROW = 72, PROW = 72;   // halfs per row
constexpr int SMEM_ATTN =
    (128 * QROW + 2 * 64 * KROW + 2 * 128 * VROW + 8 * 16 * PROW) * 2;  // 124928

__global__ __launch_bounds__(256)
void attn_kernel()
{
    extern __shared__ __half smh[];
    __half* Qs  = smh;                       // [128 q][136 d]
    __half* Ks0 = Qs + 128 * QROW;           // 2 x [64 k][136 d]
    __half* Vt0 = Ks0 + 2 * 64 * KROW;       // 2 x [128 d][72 k]
    __half* Pb  = Vt0 + 2 * 128 * VROW;      // 8 x [16 q][72 k]

    const int tid  = threadIdx.x;
    const int warp = tid >> 5, lane = tid & 31;
    const int gid  = lane >> 2, qid = lane & 3;
    const int qb   = blockIdx.x * 128;
    const int h    = blockIdx.y;
    const int b    = blockIdx.z;
    const size_t baseq = (size_t)b * S * DIM + (size_t)h * HD;
    const size_t basev = (size_t)((b * H + h) * HD) * S;
    const int q0 = warp * 16;
    __half* Pw = Pb + warp * 16 * PROW;

    auto cp_tile = [&](int kb, int buf) {
        const uint32_t kd = (uint32_t)__cvta_generic_to_shared(Ks0 + buf * 64 * KROW);
        const uint32_t vd = (uint32_t)__cvta_generic_to_shared(Vt0 + buf * 128 * VROW);
#pragma unroll
        for (int i = 0; i < 4; i++) {          // K: 64 rows x 16 chunks
            const int c = tid + i * 256;
            const int row = c >> 4, ch = c & 15;
            cp16(kd + row * 272 + ch * 16,
                 g_k + baseq + (size_t)(kb + row) * DIM + ch * 8);
        }
#pragma unroll
        for (int i = 0; i < 4; i++) {          // V^T: 128 rows x 8 chunks
            const int c = tid + i * 256;
            const int row = c >> 3, ch = c & 7;
            cp16(vd + row * 144 + ch * 16,
                 g_vt + basev + (size_t)row * S + kb + ch * 8);
        }
        asm volatile("cp.async.commit_group;");
    };

    cp_tile(0, 0);
    for (int i = tid; i < 2048; i += 256) {    // Q: 128 rows x 16 chunks
        const int row = i >> 4, ch = i & 15;
        *(uint4*)(Qs + row * QROW + ch * 8) =
            *(const uint4*)(g_q + baseq + (size_t)(qb + row) * DIM + ch * 8);
    }

    float oacc[8][2][4];
#pragma unroll
    for (int i = 0; i < 8; i++)
#pragma unroll
        for (int j = 0; j < 2; j++)
#pragma unroll
            for (int c = 0; c < 4; c++) oacc[i][j][c] = 0.f;
    float rm[4] = {-1e30f, -1e30f, -1e30f, -1e30f};
    float rl[4] = {0.f, 0.f, 0.f, 0.f};

    const uint32_t* Q32 = (const uint32_t*)Qs;
    const uint32_t* P32 = (const uint32_t*)Pw;

    const int nt = qb / 64 + 2;
    for (int t = 0; t < nt; t++) {
        const int kb = t * 64;
        const int buf = t & 1;
        if (t + 1 < nt) {
            cp_tile(kb + 64, buf ^ 1);
            asm volatile("cp.async.wait_group 1;" ::: "memory");
        } else {
            asm volatile("cp.async.wait_group 0;" ::: "memory");
        }
        __syncthreads();

        const uint32_t* K32 = (const uint32_t*)(Ks0 + buf * 64 * KROW);
        const uint32_t* V32 = (const uint32_t*)(Vt0 + buf * 128 * VROW);

        if (kb <= qb + q0 + 15) {
            // S^T = K @ Q^T
            float sacc[4][2][4];
#pragma unroll
            for (int i = 0; i < 4; i++)
#pragma unroll
                for (int j = 0; j < 2; j++)
#pragma unroll
                    for (int c = 0; c < 4; c++) sacc[i][j][c] = 0.f;

#pragma unroll
            for (int kk8 = 0; kk8 < 64; kk8 += 8) {   // 8 k-steps of 16
                const int kw = kk8 + qid;
                uint32_t a[4][4], bq[2][2];
#pragma unroll
                for (int mf = 0; mf < 4; mf++) {
                    const int r = mf * 16 + gid;
                    a[mf][0] = K32[(r    ) * 68 + kw];
                    a[mf][1] = K32[(r + 8) * 68 + kw];
                    a[mf][2] = K32[(r    ) * 68 + kw + 4];
                    a[mf][3] = K32[(r + 8) * 68 + kw + 4];
                }
#pragma unroll
                for (int nf = 0; nf < 2; nf++) {
                    const int q = q0 + nf * 8 + gid;
                    bq[nf][0] = Q32[q * 68 + kw];
                    bq[nf][1] = Q32[q * 68 + kw + 4];
                }
#pragma unroll
                for (int mf = 0; mf < 4; mf++)
#pragma unroll
                    for (int nf = 0; nf < 2; nf++)
                        mma_f16(sacc[mf][nf], a[mf], bq[nf]);
            }

            const bool diag = (kb + 63 > qb + q0);
            float mloc[4] = {-1e30f, -1e30f, -1e30f, -1e30f};
#pragma unroll
            for (int mf = 0; mf < 4; mf++)
#pragma unroll
                for (int nf = 0; nf < 2; nf++)
#pragma unroll
                    for (int ci = 0; ci < 4; ci++) {
                        float sv = sacc[mf][nf][ci] * SCALE;
                        if (diag) {
                            const int key = kb + mf * 16 + gid + ((ci >> 1) << 3);
                            const int q   = qb + q0 + nf * 8 + 2 * qid + (ci & 1);
                            if (key > q) sv = -1e30f;
                        }
                        sacc[mf][nf][ci] = sv;
                        const int j = nf * 2 + (ci & 1);
                        mloc[j] = fmaxf(mloc[j], sv);
                    }
#pragma unroll
            for (int j = 0; j < 4; j++) {
                mloc[j] = fmaxf(mloc[j], __shfl_xor_sync(0xffffffffu, mloc[j], 4));
                mloc[j] = fmaxf(mloc[j], __shfl_xor_sync(0xffffffffu, mloc[j], 8));
                mloc[j] = fmaxf(mloc[j], __shfl_xor_sync(0xffffffffu, mloc[j], 16));
            }
            float corr[4];
#pragma unroll
            for (int j = 0; j < 4; j++) {
                const float newm = fmaxf(rm[j], mloc[j]);
                corr[j] = __expf(rm[j] - newm);
                rm[j] = newm;
            }
            float psum[4] = {0.f, 0.f, 0.f, 0.f};
#pragma unroll
            for (int mf = 0; mf < 4; mf++)
#pragma unroll
                for (int nf = 0; nf < 2; nf++)
#pragma unroll
                    for (int ci = 0; ci < 4; ci++) {
                        const int j = nf * 2 + (ci & 1);
                        const float p = __expf(sacc[mf][nf][ci] - rm[j]);
                        psum[j] += p;
                        const int key = mf * 16 + gid + ((ci >> 1) << 3);
                        const int qq  = nf * 8 + 2 * qid + (ci & 1);
                        Pw[qq * PROW + key] = __float2half(p);
                    }
#pragma unroll
            for (int j = 0; j < 4; j++) {
                psum[j] += __shfl_xor_sync(0xffffffffu, psum[j], 4);
                psum[j] += __shfl_xor_sync(0xffffffffu, psum[j], 8);
                psum[j] += __shfl_xor_sync(0xffffffffu, psum[j], 16);
                rl[j] = rl[j] * corr[j] + psum[j];
            }
#pragma unroll
            for (int mfo = 0; mfo < 8; mfo++)
#pragma unroll
                for (int nf = 0; nf < 2; nf++)
#pragma unroll
                    for (int ci = 0; ci < 4; ci++)
                        oacc[mfo][nf][ci] *= corr[nf * 2 + (ci & 1)];

            __syncwarp();

            // O^T += V^T @ P
#pragma unroll
            for (int ko = 0; ko < 4; ko++) {
                const int kw = ko * 8 + qid;
                uint32_t bp[2][2];
#pragma unroll
                for (int nf = 0; nf < 2; nf++) {
                    const int q = nf * 8 + gid;
                    bp[nf][0] = P32[q * 36 + kw];
                    bp[nf][1] = P32[q * 36 + kw + 4];
                }
#pragma unroll
                for (int mfo = 0; mfo < 8; mfo++) {
                    const int d = mfo * 16 + gid;
                    uint32_t a[4];
                    a[0] = V32[(d    ) * 36 + kw];
                    a[1] = V32[(d + 8) * 36 + kw];
                    a[2] = V32[(d    ) * 36 + kw + 4];
                    a[3] = V32[(d + 8) * 36 + kw + 4];
#pragma unroll
                    for (int nf = 0; nf < 2; nf++)
                        mma_f16(oacc[mfo][nf], a, bp[nf]);
                }
            }
        }
        __syncthreads();
    }

    float inv[4];
#pragma unroll
    for (int j = 0; j < 4; j++) inv[j] = 1.f / rl[j];
#pragma unroll
    for (int mfo = 0; mfo < 8; mfo++)
#pragma unroll
        for (int nf = 0; nf < 2; nf++)
#pragma unroll
            for (int ci = 0; ci < 4; ci++) {
                const int d = mfo * 16 + gid + ((ci >> 1) << 3);
                const int q = qb + q0 + nf * 8 + 2 * qid + (ci & 1);
                g_ctx[baseq + (size_t)q * DIM + d] =
                    __float2half(oacc[mfo][nf][ci] * inv[nf * 2 + (ci & 1)]);
            }
}

// ---------------------------------------------------------------------------
// Launch
// ---------------------------------------------------------------------------
extern "C" void kernel_launch(void* const* d_in, const int* in_sizes, int n_in,
                              void* d_out, int out_size)
{
    const float* x    = (const float*)d_in[0];
    const float* cosb = (const float*)d_in[2];
    const float* sinb = (const float*)d_in[3];
    const float* wq   = (const float*)d_in[5];
    const float* bq   = (const float*)d_in[6];
    const float* wk   = (const float*)d_in[7];
    const float* bk   = (const float*)d_in[8];
    const float* wv   = (const float*)d_in[9];
    const float* bv   = (const float*)d_in[10];
    const float* wo   = (const float*)d_in[11];
    const float* bo   = (const float*)d_in[12];
    float* out = (float*)d_out;

    __half *q, *k, *vt, *ctx, *cx, *cwq, *cwk, *cwv, *cwo;
    cudaGetSymbolAddress((void**)&q,   g_q);
    cudaGetSymbolAddress((void**)&k,   g_k);
    cudaGetSymbolAddress((void**)&vt,  g_vt);
    cudaGetSymbolAddress((void**)&ctx, g_ctx);
    cudaGetSymbolAddress((void**)&cx,  c_x);
    cudaGetSymbolAddress((void**)&cwq, c_wq);
    cudaGetSymbolAddress((void**)&cwk, c_wk);
    cudaGetSymbolAddress((void**)&cwv, c_wv);
    cudaGetSymbolAddress((void**)&cwo, c_wo);

    cudaFuncSetAttribute(attn_kernel,
                         cudaFuncAttributeMaxDynamicSharedMemorySize, SMEM_ATTN);
    cudaFuncSetAttribute(gemm_f16<1>,
                         cudaFuncAttributeMaxDynamicSharedMemorySize, SMEM_GEMM);
    cudaFuncSetAttribute(gemm_f16<0>,
                         cudaFuncAttributeMaxDynamicSharedMemorySize, SMEM_GEMM);

    // fp32 -> fp16 pre-conversion
    const int nx4 = M * DIM / 4, nw4 = DIM * DIM / 4;
    cvt_kernel<<<(nx4 + 255) / 256, 256>>>((const float4*)x,  (__half2*)cx,  nx4);
    cvt_kernel<<<(nw4 + 255) / 256, 256>>>((const float4*)wq, (__half2*)cwq, nw4);
    cvt_kernel<<<(nw4 + 255) / 256, 256>>>((const float4*)wk, (__half2*)cwk, nw4);
    cvt_kernel<<<(nw4 + 255) / 256, 256>>>((const float4*)wv, (__half2*)cwv, nw4);
    cvt_kernel<<<(nw4 + 255) / 256, 256>>>((const float4*)wo, (__half2*)cwo, nw4);

    // Fused QKV projections (+bias, +RoPE for q/k; v stored transposed)
    dim3 gqkv(DIM / 128, M / 128, 3);   // (16, 32, 3)
    gemm_f16<1><<<gqkv, 256, SMEM_GEMM>>>(cx, cwq, cwk, cwv, bq, bk, bv,
                                          q, k, vt, cosb, sinb);

    dim3 adim(S / 128, H, B);           // (8, 16, 4)
    attn_kernel<<<adim, 256, SMEM_ATTN>>>();

    dim3 gdim(DIM / 128, M / 128, 1);
    gemm_f16<0><<<gdim, 256, SMEM_GEMM>>>(ctx, cwo, cwo, cwo, bo, bo, bo,
                                          out, out, out, cosb, sinb);
}